// round 7
// baseline (speedup 1.0000x reference)
#include <cuda_runtime.h>
#include <cuda_bf16.h>
#include <cuda_fp16.h>
#include <stdint.h>

#define Bn   64
#define Sn   512
#define INn  1024
#define HIDn 1024
#define G4   4096
#define Mtot 32768

// ---- device scratch ----
__device__ float g_scr[(size_t)Mtot * G4];              // x@U + bias (512MB)
__device__ float c_buf[Bn * HIDn];
__device__ float h_fin[Bn * HIDn];
__device__ int   g_flags[Sn + 1][4];                    // per-step h-chunk ready counters
__device__ __nv_bfloat16 x_hi[(size_t)Mtot * INn];
__device__ __nv_bfloat16 x_lo[(size_t)Mtot * INn];
__device__ __nv_bfloat16 u_hi[(size_t)G4 * INn];        // U^T [N][K]
__device__ __nv_bfloat16 u_lo[(size_t)G4 * INn];
__device__ __half vt_h[(size_t)G4 * HIDn];              // V^T [N][K] fp16
__device__ __half hb[2][Bn * HIDn];                     // h carried as fp16

// ---- helpers ----
__device__ __forceinline__ uint32_t smem_u32(const void* p) {
    uint32_t a;
    asm("{ .reg .u64 t; cvta.to.shared.u64 t, %1; cvt.u32.u64 %0, t; }" : "=r"(a) : "l"(p));
    return a;
}
__device__ __forceinline__ void ldsm4(uint32_t r[4], uint32_t addr) {
    asm volatile("ldmatrix.sync.aligned.m8n8.x4.shared.b16 {%0,%1,%2,%3}, [%4];"
        : "=r"(r[0]), "=r"(r[1]), "=r"(r[2]), "=r"(r[3]) : "r"(addr));
}
__device__ __forceinline__ void mma_bf16(float c[4], const uint32_t a[4],
                                         uint32_t b0, uint32_t b1) {
    asm volatile("mma.sync.aligned.m16n8k16.row.col.f32.bf16.bf16.f32 "
        "{%0,%1,%2,%3}, {%4,%5,%6,%7}, {%8,%9}, {%0,%1,%2,%3};"
        : "+f"(c[0]), "+f"(c[1]), "+f"(c[2]), "+f"(c[3])
        : "r"(a[0]), "r"(a[1]), "r"(a[2]), "r"(a[3]), "r"(b0), "r"(b1));
}
__device__ __forceinline__ void mma_f16(float c[4], const uint32_t a[4],
                                        uint32_t b0, uint32_t b1) {
    asm volatile("mma.sync.aligned.m16n8k16.row.col.f32.f16.f16.f32 "
        "{%0,%1,%2,%3}, {%4,%5,%6,%7}, {%8,%9}, {%0,%1,%2,%3};"
        : "+f"(c[0]), "+f"(c[1]), "+f"(c[2]), "+f"(c[3])
        : "r"(a[0]), "r"(a[1]), "r"(a[2]), "r"(a[3]), "r"(b0), "r"(b1));
}
__device__ __forceinline__ float sigmoid_f(float x) { return 1.0f / (1.0f + __expf(-x)); }
__device__ __forceinline__ float tanh_f(float x) { return 2.0f / (1.0f + __expf(-2.0f * x)) - 1.0f; }

// ---------------------------------------------------------------------------
__global__ void init_state_k(const float* __restrict__ h0,
                             const float* __restrict__ c0) {
    int i = blockIdx.x * blockDim.x + threadIdx.x;
    if (i < Bn * HIDn) {
        c_buf[i] = c0[i];
        hb[0][i] = __float2half_rn(h0[i]);
        h_fin[i] = h0[i];
    }
    if (i < (Sn + 1) * 4) ((int*)g_flags)[i] = (i < 4) ? 16 : 0;
}

__global__ void conv_x_k(const float* __restrict__ x) {
    size_t i = (size_t)blockIdx.x * blockDim.x + threadIdx.x;
    if (i < (size_t)Mtot * INn) {
        float v = x[i];
        __nv_bfloat16 h = __float2bfloat16_rn(v);
        x_hi[i] = h;
        x_lo[i] = __float2bfloat16_rn(v - __bfloat162float(h));
    }
}
__global__ void conv_u_k(const float* __restrict__ U) {
    size_t i = (size_t)blockIdx.x * blockDim.x + threadIdx.x;
    if (i < (size_t)G4 * INn) {
        size_t n = i / INn, k = i % INn;
        float v = U[k * G4 + n];
        __nv_bfloat16 h = __float2bfloat16_rn(v);
        u_hi[i] = h;
        u_lo[i] = __float2bfloat16_rn(v - __bfloat162float(h));
    }
}
__global__ void conv_v_k(const float* __restrict__ V) {
    size_t i = (size_t)blockIdx.x * blockDim.x + threadIdx.x;
    if (i < (size_t)G4 * HIDn) {
        size_t n = i / HIDn, k = i % HIDn;
        vt_h[i] = __float2half_rn(V[k * G4 + n]);
    }
}

// ---------------------------------------------------------------------------
// Phase 1: bf16-split HMMA GEMM (unchanged — known good).
// ---------------------------------------------------------------------------
#define SA   80
#define T1B  (128 * SA)
#define BUFB (4 * T1B)
#define SM1  (2 * BUFB)

#define P1_LOADREG(kc) do { \
    _Pragma("unroll") \
    for (int i = 0; i < 8; ++i) { \
        int e = tid + i * 256; int tl = e >> 9; int rr = (e >> 2) & 127; int c4 = e & 3; \
        const __nv_bfloat16* bp = (tl == 0) ? x_hi : (tl == 1) ? x_lo : (tl == 2) ? u_hi : u_lo; \
        int r0 = ((tl < 2) ? m0 : n0) + rr; \
        pf[i] = *(const float4*)(bp + (size_t)r0 * INn + (kc) * 32 + c4 * 8); \
    } } while (0)
#define P1_STORE(b) do { \
    _Pragma("unroll") \
    for (int i = 0; i < 8; ++i) { \
        int e = tid + i * 256; int tl = e >> 9; int rr = (e >> 2) & 127; int c4 = e & 3; \
        *(float4*)(sm + (b) * BUFB + tl * T1B + rr * SA + c4 * 16) = pf[i]; \
    } } while (0)

__global__ __launch_bounds__(256, 1) void gemm_xu_mma(const float* __restrict__ bias) {
    extern __shared__ char sm[];
    const uint32_t smb = smem_u32(sm);
    const int tid = threadIdx.x, w = tid >> 5, l = tid & 31;
    const int m0 = blockIdx.y * 128, n0 = blockIdx.x * 128;
    const int wm = w >> 1, wn = w & 1;
    const int gr = l >> 2, q = l & 3;
    const int rA = (l & 7) + ((l >> 3) & 1) * 8, cA = (l >> 4) * 16;
    const int rB = (l & 7) + ((l >> 4) & 1) * 8, cB = ((l >> 3) & 1) * 16;

    float acc[2][8][4];
#pragma unroll
    for (int a = 0; a < 2; ++a)
#pragma unroll
        for (int b = 0; b < 8; ++b)
#pragma unroll
            for (int c = 0; c < 4; ++c) acc[a][b][c] = 0.0f;

    float4 pf[8];
    P1_LOADREG(0);
    P1_STORE(0);
    P1_LOADREG(1);
    __syncthreads();

    for (int kc = 0; kc < 32; ++kc) {
        const int buf = kc & 1;
        if (kc + 1 < 32) P1_STORE(buf ^ 1);
        if (kc + 2 < 32) P1_LOADREG(kc + 2);

        const uint32_t base = smb + buf * BUFB;
#pragma unroll
        for (int ks = 0; ks < 2; ++ks) {
            uint32_t ah[2][4], al[2][4];
#pragma unroll
            for (int mfi = 0; mfi < 2; ++mfi) {
                uint32_t ra = base + (uint32_t)((wm * 32 + mfi * 16 + rA) * SA + ks * 32 + cA);
                ldsm4(ah[mfi], ra);
                ldsm4(al[mfi], ra + T1B);
            }
#pragma unroll
            for (int np = 0; np < 4; ++np) {
                uint32_t rb = base + 2 * T1B +
                              (uint32_t)((wn * 64 + np * 16 + rB) * SA + ks * 32 + cB);
                uint32_t bh[4], bl[4];
                ldsm4(bh, rb);
                ldsm4(bl, rb + T1B);
#pragma unroll
                for (int mfi = 0; mfi < 2; ++mfi) {
                    mma_bf16(acc[mfi][2 * np],     ah[mfi], bh[0], bh[1]);
                    mma_bf16(acc[mfi][2 * np + 1], ah[mfi], bh[2], bh[3]);
                    mma_bf16(acc[mfi][2 * np],     al[mfi], bh[0], bh[1]);
                    mma_bf16(acc[mfi][2 * np + 1], al[mfi], bh[2], bh[3]);
                    mma_bf16(acc[mfi][2 * np],     ah[mfi], bl[0], bl[1]);
                    mma_bf16(acc[mfi][2 * np + 1], ah[mfi], bl[2], bl[3]);
                }
            }
        }
        __syncthreads();
    }

#pragma unroll
    for (int mfi = 0; mfi < 2; ++mfi) {
#pragma unroll
        for (int nf = 0; nf < 8; ++nf) {
            int row = m0 + wm * 32 + mfi * 16 + gr;
            int col = n0 + wn * 64 + nf * 8 + 2 * q;
            float2 bz = *(const float2*)(bias + col);
            float2 w0 = make_float2(acc[mfi][nf][0] + bz.x, acc[mfi][nf][1] + bz.y);
            float2 w1 = make_float2(acc[mfi][nf][2] + bz.x, acc[mfi][nf][3] + bz.y);
            *(float2*)(g_scr + (size_t)row * G4 + col) = w0;
            *(float2*)(g_scr + (size_t)(row + 8) * G4 + col) = w1;
        }
    }
}

// ---------------------------------------------------------------------------
// Phase 2: persistent recurrence, 64 CTAs x 512 threads, 16 h-cols per CTA.
//  - V^T slice (64 gate-cols x 1024 k fp16, 129KB) resident in SMEM
//  - h in 4 chunks x 256 kcols via cp.async.cg (L2-only; no stale-L1 hazard)
//  - per-chunk producer flags (16 producers each), lane-0-only polling
// ---------------------------------------------------------------------------
#define NCTA2  64
#define NTHR2  512
#define KP2    2064                       // VT smem row stride bytes (1032 fp16)
#define HB_OFF (64 * KP2)                 // 132096
#define HROW2  528                        // 256 fp16 + 16B pad
#define HBUF2  (64 * HROW2)               // 33792
#define GSM2_O (HB_OFF + 2 * HBUF2)       // 199680
#define SM2    (GSM2_O + 64 * 68 * 4)     // 217088

#define POLL_FLAG(pt, pc) do { \
    if (l == 0) { \
        const int* _fp = &g_flags[(pt)][(pc)]; \
        int _v, _sp = 0; \
        for (;;) { \
            asm volatile("ld.acquire.gpu.global.s32 %0, [%1];" : "=r"(_v) : "l"(_fp) : "memory"); \
            if (_v >= 16) break; \
            if (++_sp > 16) { __nanosleep(64); _sp = 0; } \
        } \
    } \
    __syncwarp(); } while (0)

#define P2_ISSUE(ch) do { \
    _Pragma("unroll") \
    for (int i = 0; i < 4; ++i) { \
        int e = tid + i * 512; int rr = e >> 5; int c16 = e & 31; \
        uint32_t dst = smb + HB_OFF + ((ch) & 1) * HBUF2 + rr * HROW2 + c16 * 16; \
        const __half* src = hh + (size_t)rr * HIDn + (ch) * 256 + c16 * 8; \
        asm volatile("cp.async.cg.shared.global [%0], [%1], 16;" :: "r"(dst), "l"(src) : "memory"); \
    } \
    asm volatile("cp.async.commit_group;" ::: "memory"); } while (0)

#define P2_COMPUTE(ch) do { \
    const uint32_t ab = smb + HB_OFF + ((ch) & 1) * HBUF2 + (uint32_t)((mf * 16 + rA) * HROW2 + cA); \
    const uint32_t bb = smb + (uint32_t)((nb + rB) * KP2 + (ch) * 512 + cB); \
    _Pragma("unroll") \
    for (int ks = 0; ks < 16; ++ks) { \
        uint32_t a4[4], b4[4]; \
        ldsm4(a4, ab + ks * 32); \
        ldsm4(b4, bb + ks * 32); \
        mma_f16(acc[0], a4, b4[0], b4[1]); \
        mma_f16(acc[1], a4, b4[2], b4[3]); \
    } } while (0)

__global__ __launch_bounds__(NTHR2, 1) void lstm_persist_mma(float* __restrict__ out) {
    extern __shared__ char sm[];
    const uint32_t smb = smem_u32(sm);
    float* gsm = (float*)(sm + GSM2_O);
    const int tid = threadIdx.x, w = tid >> 5, l = tid & 31;
    const int j0 = blockIdx.x * 16;
    const int mf = w >> 2, nb = (w & 3) * 16;
    const int gr = l >> 2, q = l & 3;
    const int rA = (l & 7) + ((l >> 3) & 1) * 8, cA = (l >> 4) * 16;
    const int rB = (l & 7) + ((l >> 4) & 1) * 8, cB = ((l >> 3) & 1) * 16;
    const int my_chunk = blockIdx.x >> 4;    // h-chunk this CTA's columns feed

    // Load V^T slice (64 gate-cols x 1024 k, fp16) once: 129KB.
#pragma unroll
    for (int i = 0; i < 16; ++i) {
        int e = tid + i * 512;
        int r = e >> 7, c = e & 127;
        int gv = (r >> 4) * 1024 + j0 + (r & 15);
        *(float4*)(sm + r * KP2 + c * 16) = *(const float4*)(vt_h + (size_t)gv * HIDn + c * 8);
    }
    __syncthreads();

    for (int t = 0; t < Sn; ++t) {
        const __half* hh = hb[t & 1];

        // Prefetch this step's x@U+bias values into registers.
        float2 gpre[4];
        {
            int m = mf * 16 + gr;
            const float* gp = g_scr + ((size_t)(m * Sn + t)) * G4;
#pragma unroll
            for (int nf = 0; nf < 2; ++nf) {
                int c = nb + nf * 8 + 2 * q;
                int gcol = (c >> 4) * HIDn + j0 + (c & 15);
                gpre[nf * 2]     = *(const float2*)(gp + gcol);
                gpre[nf * 2 + 1] = *(const float2*)(gp + (size_t)8 * Sn * G4 + gcol);
            }
        }

        float acc[2][4];
#pragma unroll
        for (int a = 0; a < 2; ++a)
#pragma unroll
            for (int c = 0; c < 4; ++c) acc[a][c] = 0.0f;

        POLL_FLAG(t, 0);
        P2_ISSUE(0);
        POLL_FLAG(t, 1);
        P2_ISSUE(1);

        // ch 0
        asm volatile("cp.async.wait_group 1;" ::: "memory");
        __syncthreads();
        P2_COMPUTE(0);
        __syncthreads();
        POLL_FLAG(t, 2);
        P2_ISSUE(2);
        // ch 1
        asm volatile("cp.async.wait_group 1;" ::: "memory");
        __syncthreads();
        P2_COMPUTE(1);
        __syncthreads();
        POLL_FLAG(t, 3);
        P2_ISSUE(3);
        // ch 2
        asm volatile("cp.async.wait_group 1;" ::: "memory");
        __syncthreads();
        P2_COMPUTE(2);
        // ch 3
        asm volatile("cp.async.wait_group 0;" ::: "memory");
        __syncthreads();
        P2_COMPUTE(3);

        // Stage pre-activations into gsm [64 rows][64 gate-cols, stride 68].
#pragma unroll
        for (int nf = 0; nf < 2; ++nf) {
            int m = mf * 16 + gr;
            int c = nb + nf * 8 + 2 * q;
            gsm[m * 68 + c]           = acc[nf][0] + gpre[nf * 2].x;
            gsm[m * 68 + c + 1]       = acc[nf][1] + gpre[nf * 2].y;
            gsm[(m + 8) * 68 + c]     = acc[nf][2] + gpre[nf * 2 + 1].x;
            gsm[(m + 8) * 68 + c + 1] = acc[nf][3] + gpre[nf * 2 + 1].y;
        }
        __syncthreads();

        // Gates: 64 rows x 16 h-cols = 1024 cells, 2 per thread.
        const int nxt = (t & 1) ^ 1;
#pragma unroll
        for (int p = 0; p < 2; ++p) {
            int e  = tid + p * 512;
            int m  = e >> 4;
            int jj = e & 15;
            float gn = gsm[m * 68 + jj];
            float gi = gsm[m * 68 + 16 + jj];
            float gf = gsm[m * 68 + 32 + jj];
            float go = gsm[m * 68 + 48 + jj];
            float nv = tanh_f(gn);
            float iv = sigmoid_f(gi);
            float fv = sigmoid_f(gf);
            float ov = sigmoid_f(go);
            int idx = m * HIDn + j0 + jj;
            float cn = c_buf[idx] * fv + nv * iv;
            c_buf[idx] = cn;
            float hn = tanh_f(cn) * ov;
            out[((size_t)m * Sn + t) * HIDn + j0 + jj] = hn;
            hb[nxt][idx] = __float2half_rn(hn);
            if (t == Sn - 1) h_fin[idx] = hn;
        }

        // Publish: this CTA's h columns for step t+1 are ready.
        __syncthreads();
        if (tid == 0) {
            const int* fp = &g_flags[t + 1][my_chunk];
            asm volatile("red.release.gpu.global.add.s32 [%0], %1;"
                         :: "l"(fp), "r"(1) : "memory");
        }
    }
}

__global__ void finalize_k(float* __restrict__ out_tail) {
    int i = blockIdx.x * blockDim.x + threadIdx.x;
    if (i < Bn * HIDn) {
        out_tail[i]             = h_fin[i];
        out_tail[Bn * HIDn + i] = c_buf[i];
    }
}

extern "C" void kernel_launch(void* const* d_in, const int* in_sizes, int n_in,
                              void* d_out, int out_size) {
    const float* x    = (const float*)d_in[0];
    const float* U    = (const float*)d_in[1];
    const float* V    = (const float*)d_in[2];
    const float* bias = (const float*)d_in[3];
    const float* h0   = (const float*)d_in[4];
    const float* c0   = (const float*)d_in[5];
    float* out = (float*)d_out;

    static int attr_done = 0;
    if (!attr_done) {
        cudaFuncSetAttribute(gemm_xu_mma,
                             cudaFuncAttributeMaxDynamicSharedMemorySize, SM1);
        cudaFuncSetAttribute(lstm_persist_mma,
                             cudaFuncAttributeMaxDynamicSharedMemorySize, SM2);
        attr_done = 1;
    }

    init_state_k<<<(Bn * HIDn + 255) / 256, 256>>>(h0, c0);
    conv_x_k<<<(int)(((size_t)Mtot * INn + 255) / 256), 256>>>(x);
    conv_u_k<<<(int)(((size_t)G4 * INn + 255) / 256), 256>>>(U);
    conv_v_k<<<(int)(((size_t)G4 * HIDn + 255) / 256), 256>>>(V);

    dim3 gg(G4 / 128, Mtot / 128);
    gemm_xu_mma<<<gg, 256, SM1>>>(bias);

    lstm_persist_mma<<<NCTA2, NTHR2, SM2>>>(out);

    long long main_elems = (long long)Bn * Sn * HIDn;
    if ((long long)out_size >= main_elems + 2LL * Bn * HIDn) {
        finalize_k<<<(Bn * HIDn + 255) / 256, 256>>>(out + main_elems);
    }
}

// round 8
// speedup vs baseline: 1.1293x; 1.1293x over previous
#include <cuda_runtime.h>
#include <cuda_bf16.h>
#include <cuda_fp16.h>
#include <stdint.h>

#define Bn   64
#define Sn   512
#define INn  1024
#define HIDn 1024
#define G4   4096
#define Mtot 32768
#define NCTA 128
#define NTHR 256

// ---- device scratch ----
__device__ float g_scr[(size_t)Mtot * G4];              // x@U + bias (512MB)
__device__ float c_buf[Bn * HIDn];
__device__ float h_fin[Bn * HIDn];
__device__ int   g_flags[Sn + 1][4];                    // per-step h-chunk ready counters
__device__ __nv_bfloat16 x_hi[(size_t)Mtot * INn];
__device__ __nv_bfloat16 x_lo[(size_t)Mtot * INn];
__device__ __nv_bfloat16 u_hi[(size_t)G4 * INn];        // U^T [N][K]
__device__ __nv_bfloat16 u_lo[(size_t)G4 * INn];
__device__ __half vt_h[(size_t)G4 * HIDn];              // V^T [N][K] fp16
__device__ __half hb[2][Bn * HIDn];                     // h carried as fp16

// ---- helpers ----
__device__ __forceinline__ uint32_t smem_u32(const void* p) {
    uint32_t a;
    asm("{ .reg .u64 t; cvta.to.shared.u64 t, %1; cvt.u32.u64 %0, t; }" : "=r"(a) : "l"(p));
    return a;
}
__device__ __forceinline__ void ldsm4(uint32_t r[4], uint32_t addr) {
    asm volatile("ldmatrix.sync.aligned.m8n8.x4.shared.b16 {%0,%1,%2,%3}, [%4];"
        : "=r"(r[0]), "=r"(r[1]), "=r"(r[2]), "=r"(r[3]) : "r"(addr));
}
__device__ __forceinline__ void mma_bf16(float c[4], const uint32_t a[4],
                                         uint32_t b0, uint32_t b1) {
    asm volatile("mma.sync.aligned.m16n8k16.row.col.f32.bf16.bf16.f32 "
        "{%0,%1,%2,%3}, {%4,%5,%6,%7}, {%8,%9}, {%0,%1,%2,%3};"
        : "+f"(c[0]), "+f"(c[1]), "+f"(c[2]), "+f"(c[3])
        : "r"(a[0]), "r"(a[1]), "r"(a[2]), "r"(a[3]), "r"(b0), "r"(b1));
}
__device__ __forceinline__ void mma_f16(float c[4], const uint32_t a[4],
                                        uint32_t b0, uint32_t b1) {
    asm volatile("mma.sync.aligned.m16n8k16.row.col.f32.f16.f16.f32 "
        "{%0,%1,%2,%3}, {%4,%5,%6,%7}, {%8,%9}, {%0,%1,%2,%3};"
        : "+f"(c[0]), "+f"(c[1]), "+f"(c[2]), "+f"(c[3])
        : "r"(a[0]), "r"(a[1]), "r"(a[2]), "r"(a[3]), "r"(b0), "r"(b1));
}
__device__ __forceinline__ float sigmoid_f(float x) { return 1.0f / (1.0f + __expf(-x)); }
__device__ __forceinline__ float tanh_f(float x) { return 2.0f / (1.0f + __expf(-2.0f * x)) - 1.0f; }

// ---------------------------------------------------------------------------
__global__ void init_state_k(const float* __restrict__ h0,
                             const float* __restrict__ c0) {
    int i = blockIdx.x * blockDim.x + threadIdx.x;
    if (i < Bn * HIDn) {
        c_buf[i] = c0[i];
        hb[0][i] = __float2half_rn(h0[i]);
        h_fin[i] = h0[i];
    }
    if (i < (Sn + 1) * 4) ((int*)g_flags)[i] = (i < 4) ? 32 : 0;
}

__global__ void conv_x_k(const float* __restrict__ x) {
    size_t i = (size_t)blockIdx.x * blockDim.x + threadIdx.x;
    if (i < (size_t)Mtot * INn) {
        float v = x[i];
        __nv_bfloat16 h = __float2bfloat16_rn(v);
        x_hi[i] = h;
        x_lo[i] = __float2bfloat16_rn(v - __bfloat162float(h));
    }
}
__global__ void conv_u_k(const float* __restrict__ U) {
    size_t i = (size_t)blockIdx.x * blockDim.x + threadIdx.x;
    if (i < (size_t)G4 * INn) {
        size_t n = i / INn, k = i % INn;
        float v = U[k * G4 + n];
        __nv_bfloat16 h = __float2bfloat16_rn(v);
        u_hi[i] = h;
        u_lo[i] = __float2bfloat16_rn(v - __bfloat162float(h));
    }
}
__global__ void conv_v_k(const float* __restrict__ V) {
    size_t i = (size_t)blockIdx.x * blockDim.x + threadIdx.x;
    if (i < (size_t)G4 * HIDn) {
        size_t n = i / HIDn, k = i % HIDn;
        vt_h[i] = __float2half_rn(V[k * G4 + n]);
    }
}

// ---------------------------------------------------------------------------
// Phase 1: bf16-split HMMA GEMM (unchanged — known good).
// ---------------------------------------------------------------------------
#define SA   80
#define T1B  (128 * SA)
#define BUFB (4 * T1B)
#define SM1  (2 * BUFB)

#define P1_LOADREG(kc) do { \
    _Pragma("unroll") \
    for (int i = 0; i < 8; ++i) { \
        int e = tid + i * 256; int tl = e >> 9; int rr = (e >> 2) & 127; int c4 = e & 3; \
        const __nv_bfloat16* bp = (tl == 0) ? x_hi : (tl == 1) ? x_lo : (tl == 2) ? u_hi : u_lo; \
        int r0 = ((tl < 2) ? m0 : n0) + rr; \
        pf[i] = *(const float4*)(bp + (size_t)r0 * INn + (kc) * 32 + c4 * 8); \
    } } while (0)
#define P1_STORE(b) do { \
    _Pragma("unroll") \
    for (int i = 0; i < 8; ++i) { \
        int e = tid + i * 256; int tl = e >> 9; int rr = (e >> 2) & 127; int c4 = e & 3; \
        *(float4*)(sm + (b) * BUFB + tl * T1B + rr * SA + c4 * 16) = pf[i]; \
    } } while (0)

__global__ __launch_bounds__(256, 1) void gemm_xu_mma(const float* __restrict__ bias) {
    extern __shared__ char sm[];
    const uint32_t smb = smem_u32(sm);
    const int tid = threadIdx.x, w = tid >> 5, l = tid & 31;
    const int m0 = blockIdx.y * 128, n0 = blockIdx.x * 128;
    const int wm = w >> 1, wn = w & 1;
    const int gr = l >> 2, q = l & 3;
    const int rA = (l & 7) + ((l >> 3) & 1) * 8, cA = (l >> 4) * 16;
    const int rB = (l & 7) + ((l >> 4) & 1) * 8, cB = ((l >> 3) & 1) * 16;

    float acc[2][8][4];
#pragma unroll
    for (int a = 0; a < 2; ++a)
#pragma unroll
        for (int b = 0; b < 8; ++b)
#pragma unroll
            for (int c = 0; c < 4; ++c) acc[a][b][c] = 0.0f;

    float4 pf[8];
    P1_LOADREG(0);
    P1_STORE(0);
    P1_LOADREG(1);
    __syncthreads();

    for (int kc = 0; kc < 32; ++kc) {
        const int buf = kc & 1;
        if (kc + 1 < 32) P1_STORE(buf ^ 1);
        if (kc + 2 < 32) P1_LOADREG(kc + 2);

        const uint32_t base = smb + buf * BUFB;
#pragma unroll
        for (int ks = 0; ks < 2; ++ks) {
            uint32_t ah[2][4], al[2][4];
#pragma unroll
            for (int mfi = 0; mfi < 2; ++mfi) {
                uint32_t ra = base + (uint32_t)((wm * 32 + mfi * 16 + rA) * SA + ks * 32 + cA);
                ldsm4(ah[mfi], ra);
                ldsm4(al[mfi], ra + T1B);
            }
#pragma unroll
            for (int np = 0; np < 4; ++np) {
                uint32_t rb = base + 2 * T1B +
                              (uint32_t)((wn * 64 + np * 16 + rB) * SA + ks * 32 + cB);
                uint32_t bh[4], bl[4];
                ldsm4(bh, rb);
                ldsm4(bl, rb + T1B);
#pragma unroll
                for (int mfi = 0; mfi < 2; ++mfi) {
                    mma_bf16(acc[mfi][2 * np],     ah[mfi], bh[0], bh[1]);
                    mma_bf16(acc[mfi][2 * np + 1], ah[mfi], bh[2], bh[3]);
                    mma_bf16(acc[mfi][2 * np],     al[mfi], bh[0], bh[1]);
                    mma_bf16(acc[mfi][2 * np + 1], al[mfi], bh[2], bh[3]);
                    mma_bf16(acc[mfi][2 * np],     ah[mfi], bl[0], bl[1]);
                    mma_bf16(acc[mfi][2 * np + 1], ah[mfi], bl[2], bl[3]);
                }
            }
        }
        __syncthreads();
    }

#pragma unroll
    for (int mfi = 0; mfi < 2; ++mfi) {
#pragma unroll
        for (int nf = 0; nf < 8; ++nf) {
            int row = m0 + wm * 32 + mfi * 16 + gr;
            int col = n0 + wn * 64 + nf * 8 + 2 * q;
            float2 bz = *(const float2*)(bias + col);
            float2 w0 = make_float2(acc[mfi][nf][0] + bz.x, acc[mfi][nf][1] + bz.y);
            float2 w1 = make_float2(acc[mfi][nf][2] + bz.x, acc[mfi][nf][3] + bz.y);
            *(float2*)(g_scr + (size_t)row * G4 + col) = w0;
            *(float2*)(g_scr + (size_t)(row + 8) * G4 + col) = w1;
        }
    }
}

// ---------------------------------------------------------------------------
// Phase 2: persistent recurrence (R6 layout: 128 CTAs x 256 thr, 8 h-cols),
// with shortened step critical path:
//  - early flag release (before out/c stores)
//  - cross-step pipelining: next step's chunk-0 cp.async issued in epilogue
//  - cp.async.cg (L2-only), lane-0 polling
// ---------------------------------------------------------------------------
#define KP     2064                       // VT smem row stride bytes
#define HB_OFF 66048                      // 32*KP
#define HROW   528                        // 256 fp16 + 16B pad
#define HBUFB  (64 * HROW)                // 33792
#define GSM_O  (HB_OFF + 4 * HBUFB)       // 201216
#define SM2    (GSM_O + 64 * 33 * 4)      // 209664

#define POLL_FLAG(pt, pc) do { \
    if (l == 0) { \
        const int* _fp = &g_flags[(pt)][(pc)]; \
        int _v, _sp = 0; \
        for (;;) { \
            asm volatile("ld.acquire.gpu.global.s32 %0, [%1];" : "=r"(_v) : "l"(_fp) : "memory"); \
            if (_v >= 32) break; \
            if (++_sp > 16) { __nanosleep(64); _sp = 0; } \
        } \
    } \
    __syncwarp(); } while (0)

#define P2_ISSUE(ch, hptr) do { \
    _Pragma("unroll") \
    for (int i = 0; i < 8; ++i) { \
        int e = tid + i * 256; int rr = e >> 5; int c16 = e & 31; \
        uint32_t dst = smb + HB_OFF + (ch) * HBUFB + rr * HROW + c16 * 16; \
        const __half* src = (hptr) + (size_t)rr * HIDn + (ch) * 256 + c16 * 8; \
        asm volatile("cp.async.cg.shared.global [%0], [%1], 16;" :: "r"(dst), "l"(src) : "memory"); \
    } \
    asm volatile("cp.async.commit_group;" ::: "memory"); } while (0)

#define P2_COMPUTE(ch) do { \
    const uint32_t ab = smb + HB_OFF + (ch) * HBUFB + (uint32_t)((mf * 16 + rA) * HROW + cA); \
    const uint32_t bb = smb + (uint32_t)((nb + rB) * KP + (ch) * 512 + cB); \
    _Pragma("unroll") \
    for (int ks = 0; ks < 16; ++ks) { \
        uint32_t a4[4], b4[4]; \
        ldsm4(a4, ab + ks * 32); \
        ldsm4(b4, bb + ks * 32); \
        mma_f16(acc[0], a4, b4[0], b4[1]); \
        mma_f16(acc[1], a4, b4[2], b4[3]); \
    } } while (0)

__global__ __launch_bounds__(NTHR, 1) void lstm_persist_mma(float* __restrict__ out) {
    extern __shared__ char sm[];
    const uint32_t smb = smem_u32(sm);
    float* gsm = (float*)(sm + GSM_O);
    const int tid = threadIdx.x, w = tid >> 5, l = tid & 31;
    const int j0 = blockIdx.x * 8;
    const int mf = w >> 1, nb = (w & 1) * 16;
    const int gr = l >> 2, q = l & 3;
    const int rA = (l & 7) + ((l >> 3) & 1) * 8, cA = (l >> 4) * 16;
    const int rB = (l & 7) + ((l >> 4) & 1) * 8, cB = ((l >> 3) & 1) * 16;
    const int my_chunk = blockIdx.x >> 5;    // which h-chunk this CTA produces

    // Load V^T slice (32 gate-cols x 1024 k, fp16) once: 64KB.
#pragma unroll
    for (int i = 0; i < 16; ++i) {
        int e = tid + i * 256;
        int r = e >> 7, c = e & 127;
        int gv = (r >> 3) * 1024 + j0 + (r & 7);
        *(float4*)(sm + r * KP + c * 16) = *(const float4*)(vt_h + (size_t)gv * HIDn + c * 8);
    }
    __syncthreads();

    // Prologue: issue chunk 0 of step 0.
    POLL_FLAG(0, 0);
    P2_ISSUE(0, hb[0]);

    for (int t = 0; t < Sn; ++t) {
        const __half* hh = hb[t & 1];
        const int nxt = (t & 1) ^ 1;

        // Prefetch this step's x@U+bias values into registers (DRAM latency).
        float2 gpre[4];
        {
            int m = mf * 16 + gr;
            const float* gp = g_scr + ((size_t)(m * Sn + t)) * G4;
#pragma unroll
            for (int nf = 0; nf < 2; ++nf) {
                int c = nb + nf * 8 + 2 * q;
                int gcol = (c >> 3) * HIDn + j0 + (c & 7);
                gpre[nf * 2]     = *(const float2*)(gp + gcol);
                gpre[nf * 2 + 1] = *(const float2*)(gp + (size_t)8 * Sn * G4 + gcol);
            }
        }

        float acc[2][4];
#pragma unroll
        for (int a = 0; a < 2; ++a)
#pragma unroll
            for (int c = 0; c < 4; ++c) acc[a][c] = 0.0f;

        POLL_FLAG(t, 1);
        P2_ISSUE(1, hh);

        // ch 0
        asm volatile("cp.async.wait_group 1;" ::: "memory");
        __syncthreads();
        P2_COMPUTE(0);
        POLL_FLAG(t, 2);
        P2_ISSUE(2, hh);
        // ch 1
        asm volatile("cp.async.wait_group 1;" ::: "memory");
        __syncthreads();
        P2_COMPUTE(1);
        POLL_FLAG(t, 3);
        P2_ISSUE(3, hh);
        // ch 2
        asm volatile("cp.async.wait_group 1;" ::: "memory");
        __syncthreads();
        P2_COMPUTE(2);
        // ch 3
        asm volatile("cp.async.wait_group 0;" ::: "memory");
        __syncthreads();
        P2_COMPUTE(3);

        // Stage pre-activations into gsm.
#pragma unroll
        for (int nf = 0; nf < 2; ++nf) {
            int m = mf * 16 + gr;
            int c = nb + nf * 8 + 2 * q;
            gsm[m * 33 + c]           = acc[nf][0] + gpre[nf * 2].x;
            gsm[m * 33 + c + 1]       = acc[nf][1] + gpre[nf * 2].y;
            gsm[(m + 8) * 33 + c]     = acc[nf][2] + gpre[nf * 2 + 1].x;
            gsm[(m + 8) * 33 + c + 1] = acc[nf][3] + gpre[nf * 2 + 1].y;
        }
        __syncthreads();

        // Gates: compute in registers, store ONLY hb (critical path), defer rest.
        float cnr[2], hnr[2];
        int   idxr[2];
#pragma unroll
        for (int p = 0; p < 2; ++p) {
            int e  = tid + p * 256;
            int m  = e >> 3;
            int jj = e & 7;
            float gn = gsm[m * 33 + jj];
            float gi = gsm[m * 33 + 8 + jj];
            float gf = gsm[m * 33 + 16 + jj];
            float go = gsm[m * 33 + 24 + jj];
            float nv = tanh_f(gn);
            float iv = sigmoid_f(gi);
            float fv = sigmoid_f(gf);
            float ov = sigmoid_f(go);
            int idx = m * HIDn + j0 + jj;
            float cn = c_buf[idx] * fv + nv * iv;
            float hn = tanh_f(cn) * ov;
            hb[nxt][idx] = __float2half_rn(hn);
            cnr[p] = cn; hnr[p] = hn; idxr[p] = idx;
        }

        // Publish early: h columns for step t+1 are ready.
        __syncthreads();
        if (tid == 0) {
            const int* fp = &g_flags[t + 1][my_chunk];
            asm volatile("red.release.gpu.global.add.s32 [%0], %1;"
                         :: "l"(fp), "r"(1) : "memory");
        }

        // Deferred stores (off the inter-CTA critical path).
#pragma unroll
        for (int p = 0; p < 2; ++p) {
            int e  = tid + p * 256;
            int m  = e >> 3;
            int jj = e & 7;
            c_buf[idxr[p]] = cnr[p];
            out[((size_t)m * Sn + t) * HIDn + j0 + jj] = hnr[p];
            if (t == Sn - 1) h_fin[idxr[p]] = hnr[p];
        }

        // Cross-step pipelining: issue next step's chunk 0 now (buffer 0 free).
        if (t + 1 < Sn) {
            POLL_FLAG(t + 1, 0);
            P2_ISSUE(0, hb[nxt]);
        }
    }
}

__global__ void finalize_k(float* __restrict__ out_tail) {
    int i = blockIdx.x * blockDim.x + threadIdx.x;
    if (i < Bn * HIDn) {
        out_tail[i]             = h_fin[i];
        out_tail[Bn * HIDn + i] = c_buf[i];
    }
}

extern "C" void kernel_launch(void* const* d_in, const int* in_sizes, int n_in,
                              void* d_out, int out_size) {
    const float* x    = (const float*)d_in[0];
    const float* U    = (const float*)d_in[1];
    const float* V    = (const float*)d_in[2];
    const float* bias = (const float*)d_in[3];
    const float* h0   = (const float*)d_in[4];
    const float* c0   = (const float*)d_in[5];
    float* out = (float*)d_out;

    static int attr_done = 0;
    if (!attr_done) {
        cudaFuncSetAttribute(gemm_xu_mma,
                             cudaFuncAttributeMaxDynamicSharedMemorySize, SM1);
        cudaFuncSetAttribute(lstm_persist_mma,
                             cudaFuncAttributeMaxDynamicSharedMemorySize, SM2);
        attr_done = 1;
    }

    init_state_k<<<(Bn * HIDn + 255) / 256, 256>>>(h0, c0);
    conv_x_k<<<(int)(((size_t)Mtot * INn + 255) / 256), 256>>>(x);
    conv_u_k<<<(int)(((size_t)G4 * INn + 255) / 256), 256>>>(U);
    conv_v_k<<<(int)(((size_t)G4 * HIDn + 255) / 256), 256>>>(V);

    dim3 gg(G4 / 128, Mtot / 128);
    gemm_xu_mma<<<gg, 256, SM1>>>(bias);

    lstm_persist_mma<<<NCTA, NTHR, SM2>>>(out);

    long long main_elems = (long long)Bn * Sn * HIDn;
    if ((long long)out_size >= main_elems + 2LL * Bn * HIDn) {
        finalize_k<<<(Bn * HIDn + 255) / 256, 256>>>(out + main_elems);
    }
}

// round 9
// speedup vs baseline: 1.3660x; 1.2096x over previous
#include <cuda_runtime.h>
#include <cuda_bf16.h>
#include <cuda_fp16.h>
#include <stdint.h>

#define Bn   64
#define Sn   512
#define INn  1024
#define HIDn 1024
#define G4   4096
#define Mtot 32768
#define NCTA 128
#define NTHR 256

// ---- device scratch ----
__device__ float g_scr[(size_t)Mtot * G4];              // x@U + bias (512MB)
__device__ float c_buf[Bn * HIDn];
__device__ float h_fin[Bn * HIDn];
__device__ int   g_flags[Sn + 1][2];                    // per-step per-group ready counters
__device__ __nv_bfloat16 x_hi[(size_t)Mtot * INn];
__device__ __nv_bfloat16 x_lo[(size_t)Mtot * INn];
__device__ __nv_bfloat16 u_hi[(size_t)G4 * INn];        // U^T [N][K]
__device__ __nv_bfloat16 u_lo[(size_t)G4 * INn];
__device__ __half vt_h[(size_t)G4 * HIDn];              // V^T [N][K] fp16
__device__ __half hb[2][Bn * HIDn];                     // h carried as fp16

// ---- helpers ----
__device__ __forceinline__ uint32_t smem_u32(const void* p) {
    uint32_t a;
    asm("{ .reg .u64 t; cvta.to.shared.u64 t, %1; cvt.u32.u64 %0, t; }" : "=r"(a) : "l"(p));
    return a;
}
__device__ __forceinline__ void ldsm4(uint32_t r[4], uint32_t addr) {
    asm volatile("ldmatrix.sync.aligned.m8n8.x4.shared.b16 {%0,%1,%2,%3}, [%4];"
        : "=r"(r[0]), "=r"(r[1]), "=r"(r[2]), "=r"(r[3]) : "r"(addr));
}
__device__ __forceinline__ void mma_bf16(float c[4], const uint32_t a[4],
                                         uint32_t b0, uint32_t b1) {
    asm volatile("mma.sync.aligned.m16n8k16.row.col.f32.bf16.bf16.f32 "
        "{%0,%1,%2,%3}, {%4,%5,%6,%7}, {%8,%9}, {%0,%1,%2,%3};"
        : "+f"(c[0]), "+f"(c[1]), "+f"(c[2]), "+f"(c[3])
        : "r"(a[0]), "r"(a[1]), "r"(a[2]), "r"(a[3]), "r"(b0), "r"(b1));
}
__device__ __forceinline__ void mma_f16(float c[4], const uint32_t a[4],
                                        uint32_t b0, uint32_t b1) {
    asm volatile("mma.sync.aligned.m16n8k16.row.col.f32.f16.f16.f32 "
        "{%0,%1,%2,%3}, {%4,%5,%6,%7}, {%8,%9}, {%0,%1,%2,%3};"
        : "+f"(c[0]), "+f"(c[1]), "+f"(c[2]), "+f"(c[3])
        : "r"(a[0]), "r"(a[1]), "r"(a[2]), "r"(a[3]), "r"(b0), "r"(b1));
}
__device__ __forceinline__ float sigmoid_f(float x) { return 1.0f / (1.0f + __expf(-x)); }
__device__ __forceinline__ float tanh_f(float x) { return 2.0f / (1.0f + __expf(-2.0f * x)) - 1.0f; }

// ---------------------------------------------------------------------------
__global__ void conv_x_k(const float* __restrict__ x) {
    size_t i = (size_t)blockIdx.x * blockDim.x + threadIdx.x;
    if (i < (size_t)Mtot * INn) {
        float v = x[i];
        __nv_bfloat16 h = __float2bfloat16_rn(v);
        x_hi[i] = h;
        x_lo[i] = __float2bfloat16_rn(v - __bfloat162float(h));
    }
}
// Merged: U^T hi/lo, V^T fp16, state init, flag init. (Keeps launch count low
// so lstm_persist lands in ncu's capture slot.)
__global__ void conv_uv_init_k(const float* __restrict__ U,
                               const float* __restrict__ V,
                               const float* __restrict__ h0,
                               const float* __restrict__ c0) {
    size_t i = (size_t)blockIdx.x * blockDim.x + threadIdx.x;
    const size_t NU = (size_t)G4 * INn;
    if (i < NU) {
        size_t n = i / INn, k = i % INn;
        float v = U[k * G4 + n];
        __nv_bfloat16 h = __float2bfloat16_rn(v);
        u_hi[i] = h;
        u_lo[i] = __float2bfloat16_rn(v - __bfloat162float(h));
    } else if (i < 2 * NU) {
        size_t j = i - NU;
        size_t n = j / HIDn, k = j % HIDn;
        vt_h[j] = __float2half_rn(V[k * G4 + n]);
    }
    if (i < Bn * HIDn) {
        c_buf[i] = c0[i];
        hb[0][i] = __float2half_rn(h0[i]);
        h_fin[i] = h0[i];
    }
    if (i < (Sn + 1) * 2) ((int*)g_flags)[i] = (i < 2) ? 64 : 0;
}

// ---------------------------------------------------------------------------
// Phase 1: bf16-split HMMA GEMM (unchanged — known good).
// ---------------------------------------------------------------------------
#define SA   80
#define T1B  (128 * SA)
#define BUFB (4 * T1B)
#define SM1  (2 * BUFB)

#define P1_LOADREG(kc) do { \
    _Pragma("unroll") \
    for (int i = 0; i < 8; ++i) { \
        int e = tid + i * 256; int tl = e >> 9; int rr = (e >> 2) & 127; int c4 = e & 3; \
        const __nv_bfloat16* bp = (tl == 0) ? x_hi : (tl == 1) ? x_lo : (tl == 2) ? u_hi : u_lo; \
        int r0 = ((tl < 2) ? m0 : n0) + rr; \
        pf[i] = *(const float4*)(bp + (size_t)r0 * INn + (kc) * 32 + c4 * 8); \
    } } while (0)
#define P1_STORE(b) do { \
    _Pragma("unroll") \
    for (int i = 0; i < 8; ++i) { \
        int e = tid + i * 256; int tl = e >> 9; int rr = (e >> 2) & 127; int c4 = e & 3; \
        *(float4*)(sm + (b) * BUFB + tl * T1B + rr * SA + c4 * 16) = pf[i]; \
    } } while (0)

__global__ __launch_bounds__(256, 1) void gemm_xu_mma(const float* __restrict__ bias) {
    extern __shared__ char sm[];
    const uint32_t smb = smem_u32(sm);
    const int tid = threadIdx.x, w = tid >> 5, l = tid & 31;
    const int m0 = blockIdx.y * 128, n0 = blockIdx.x * 128;
    const int wm = w >> 1, wn = w & 1;
    const int gr = l >> 2, q = l & 3;
    const int rA = (l & 7) + ((l >> 3) & 1) * 8, cA = (l >> 4) * 16;
    const int rB = (l & 7) + ((l >> 4) & 1) * 8, cB = ((l >> 3) & 1) * 16;

    float acc[2][8][4];
#pragma unroll
    for (int a = 0; a < 2; ++a)
#pragma unroll
        for (int b = 0; b < 8; ++b)
#pragma unroll
            for (int c = 0; c < 4; ++c) acc[a][b][c] = 0.0f;

    float4 pf[8];
    P1_LOADREG(0);
    P1_STORE(0);
    P1_LOADREG(1);
    __syncthreads();

    for (int kc = 0; kc < 32; ++kc) {
        const int buf = kc & 1;
        if (kc + 1 < 32) P1_STORE(buf ^ 1);
        if (kc + 2 < 32) P1_LOADREG(kc + 2);

        const uint32_t base = smb + buf * BUFB;
#pragma unroll
        for (int ks = 0; ks < 2; ++ks) {
            uint32_t ah[2][4], al[2][4];
#pragma unroll
            for (int mfi = 0; mfi < 2; ++mfi) {
                uint32_t ra = base + (uint32_t)((wm * 32 + mfi * 16 + rA) * SA + ks * 32 + cA);
                ldsm4(ah[mfi], ra);
                ldsm4(al[mfi], ra + T1B);
            }
#pragma unroll
            for (int np = 0; np < 4; ++np) {
                uint32_t rb = base + 2 * T1B +
                              (uint32_t)((wn * 64 + np * 16 + rB) * SA + ks * 32 + cB);
                uint32_t bh[4], bl[4];
                ldsm4(bh, rb);
                ldsm4(bl, rb + T1B);
#pragma unroll
                for (int mfi = 0; mfi < 2; ++mfi) {
                    mma_bf16(acc[mfi][2 * np],     ah[mfi], bh[0], bh[1]);
                    mma_bf16(acc[mfi][2 * np + 1], ah[mfi], bh[2], bh[3]);
                    mma_bf16(acc[mfi][2 * np],     al[mfi], bh[0], bh[1]);
                    mma_bf16(acc[mfi][2 * np + 1], al[mfi], bh[2], bh[3]);
                    mma_bf16(acc[mfi][2 * np],     ah[mfi], bl[0], bl[1]);
                    mma_bf16(acc[mfi][2 * np + 1], ah[mfi], bl[2], bl[3]);
                }
            }
        }
        __syncthreads();
    }

#pragma unroll
    for (int mfi = 0; mfi < 2; ++mfi) {
#pragma unroll
        for (int nf = 0; nf < 8; ++nf) {
            int row = m0 + wm * 32 + mfi * 16 + gr;
            int col = n0 + wn * 64 + nf * 8 + 2 * q;
            float2 bz = *(const float2*)(bias + col);
            float2 w0 = make_float2(acc[mfi][nf][0] + bz.x, acc[mfi][nf][1] + bz.y);
            float2 w1 = make_float2(acc[mfi][nf][2] + bz.x, acc[mfi][nf][3] + bz.y);
            *(float2*)(g_scr + (size_t)row * G4 + col) = w0;
            *(float2*)(g_scr + (size_t)(row + 8) * G4 + col) = w1;
        }
    }
}

// ---------------------------------------------------------------------------
// Phase 2: BATCH-SPLIT persistent recurrence.
// 2 independent groups (batch rows 0-31 / 32-63), 64 CTAs each.
// Each CTA: 16 h-cols (64 gate-cols), V slice 129KB resident in SMEM.
// One flag per group per step; h (64KB/group) in 2 chunks of 32KB.
// ---------------------------------------------------------------------------
#define KP2    2064                        // VT smem row stride bytes
#define HB_OFF (64 * KP2)                  // 132096
#define HROW   1040                        // 512 fp16 + 16B pad
#define HBUF   (32 * HROW)                 // 33280
#define GSM_O  (HB_OFF + 2 * HBUF)         // 198656
#define SM2    (GSM_O + 32 * 68 * 4)       // 207360

#define POLL_FLAG(pt) do { \
    if (l == 0) { \
        const int* _fp = &g_flags[(pt)][gid]; \
        int _v, _sp = 0; \
        for (;;) { \
            asm volatile("ld.acquire.gpu.global.s32 %0, [%1];" : "=r"(_v) : "l"(_fp) : "memory"); \
            if (_v >= 64) break; \
            if (++_sp > 16) { __nanosleep(64); _sp = 0; } \
        } \
    } \
    __syncwarp(); } while (0)

#define P2_ISSUE(ch) do { \
    _Pragma("unroll") \
    for (int i = 0; i < 8; ++i) { \
        int e = tid + i * 256; int rr = e >> 6; int c16 = e & 63; \
        uint32_t dst = smb + HB_OFF + (ch) * HBUF + rr * HROW + c16 * 16; \
        const __half* src = hh + (size_t)rr * HIDn + (ch) * 512 + c16 * 8; \
        asm volatile("cp.async.cg.shared.global [%0], [%1], 16;" :: "r"(dst), "l"(src) : "memory"); \
    } \
    asm volatile("cp.async.commit_group;" ::: "memory"); } while (0)

#define P2_COMPUTE(ch) do { \
    const uint32_t ab = smb + HB_OFF + (ch) * HBUF + (uint32_t)((mf * 16 + rA) * HROW + cA); \
    const uint32_t bb = smb + (uint32_t)((nb + rB) * KP2 + (ch) * 1024 + cB); \
    _Pragma("unroll") \
    for (int ks = 0; ks < 32; ++ks) { \
        uint32_t a4[4], b4[4]; \
        ldsm4(a4, ab + ks * 32); \
        ldsm4(b4, bb + ks * 32); \
        mma_f16(acc[0], a4, b4[0], b4[1]); \
        mma_f16(acc[1], a4, b4[2], b4[3]); \
    } } while (0)

__global__ __launch_bounds__(NTHR, 1) void lstm_persist_mma(float* __restrict__ out) {
    extern __shared__ char sm[];
    const uint32_t smb = smem_u32(sm);
    float* gsm = (float*)(sm + GSM_O);
    const int tid = threadIdx.x, w = tid >> 5, l = tid & 31;
    const int gid   = blockIdx.x & 1;        // batch group
    const int cid   = blockIdx.x >> 1;       // 0..63 within group
    const int j0    = cid * 16;              // h-col base
    const int rbase = gid * 32;              // batch row base
    const int mf = w >> 2, nb = (w & 3) * 16;
    const int gr = l >> 2, q = l & 3;
    const int rA = (l & 7) + ((l >> 3) & 1) * 8, cA = (l >> 4) * 16;
    const int rB = (l & 7) + ((l >> 4) & 1) * 8, cB = ((l >> 3) & 1) * 16;

    // Load V^T slice (64 gate-cols x 1024 k, fp16) once: 128KB.
#pragma unroll
    for (int i = 0; i < 32; ++i) {
        int e = tid + i * 256;
        int r = e >> 7, c = e & 127;
        int gv = (r >> 4) * 1024 + j0 + (r & 15);
        *(float4*)(sm + r * KP2 + c * 16) = *(const float4*)(vt_h + (size_t)gv * HIDn + c * 8);
    }
    __syncthreads();

    for (int t = 0; t < Sn; ++t) {
        const __half* hh  = hb[t & 1] + (size_t)rbase * HIDn;
        const int     nxt = (t & 1) ^ 1;

        // Prefetch x@U+bias (independent of flags; overlaps poll).
        float2 gpre[4];
        {
            int m = rbase + mf * 16 + gr;
            const float* gp = g_scr + ((size_t)(m * Sn + t)) * G4;
#pragma unroll
            for (int nf = 0; nf < 2; ++nf) {
                int c = nb + nf * 8 + 2 * q;
                int gcol = (c >> 4) * HIDn + j0 + (c & 15);
                gpre[nf * 2]     = *(const float2*)(gp + gcol);
                gpre[nf * 2 + 1] = *(const float2*)(gp + (size_t)8 * Sn * G4 + gcol);
            }
        }

        float acc[2][4];
#pragma unroll
        for (int a = 0; a < 2; ++a)
#pragma unroll
            for (int c = 0; c < 4; ++c) acc[a][c] = 0.0f;

        POLL_FLAG(t);
        P2_ISSUE(0);
        P2_ISSUE(1);

        asm volatile("cp.async.wait_group 1;" ::: "memory");
        __syncthreads();
        P2_COMPUTE(0);
        asm volatile("cp.async.wait_group 0;" ::: "memory");
        __syncthreads();
        P2_COMPUTE(1);

        // Stage pre-activations into gsm [32 rows][64 gate-cols, stride 68].
#pragma unroll
        for (int nf = 0; nf < 2; ++nf) {
            int m = mf * 16 + gr;
            int c = nb + nf * 8 + 2 * q;
            gsm[m * 68 + c]           = acc[nf][0] + gpre[nf * 2].x;
            gsm[m * 68 + c + 1]       = acc[nf][1] + gpre[nf * 2].y;
            gsm[(m + 8) * 68 + c]     = acc[nf][2] + gpre[nf * 2 + 1].x;
            gsm[(m + 8) * 68 + c + 1] = acc[nf][3] + gpre[nf * 2 + 1].y;
        }
        __syncthreads();

        // Gates: 32 rows x 16 h-cols = 512 cells, 2 per thread.
        float cnr[2], hnr[2];
        int   idxr[2];
#pragma unroll
        for (int p = 0; p < 2; ++p) {
            int e  = tid + p * 256;
            int m  = e >> 4;
            int jj = e & 15;
            float gn = gsm[m * 68 + jj];
            float gi = gsm[m * 68 + 16 + jj];
            float gf = gsm[m * 68 + 32 + jj];
            float go = gsm[m * 68 + 48 + jj];
            float nv = tanh_f(gn);
            float iv = sigmoid_f(gi);
            float fv = sigmoid_f(gf);
            float ov = sigmoid_f(go);
            int idx = (rbase + m) * HIDn + j0 + jj;
            float cn = c_buf[idx] * fv + nv * iv;
            float hn = tanh_f(cn) * ov;
            hb[nxt][idx] = __float2half_rn(hn);
            cnr[p] = cn; hnr[p] = hn; idxr[p] = idx;
        }

        // Publish: this CTA's h cols for step t+1 are ready (group flag).
        __syncthreads();
        if (tid == 0) {
            const int* fp = &g_flags[t + 1][gid];
            asm volatile("red.release.gpu.global.add.s32 [%0], %1;"
                         :: "l"(fp), "r"(1) : "memory");
        }

        // Deferred stores (off the inter-CTA critical path).
#pragma unroll
        for (int p = 0; p < 2; ++p) {
            int e  = tid + p * 256;
            int m  = e >> 4;
            int jj = e & 15;
            c_buf[idxr[p]] = cnr[p];
            out[((size_t)(rbase + m) * Sn + t) * HIDn + j0 + jj] = hnr[p];
            if (t == Sn - 1) h_fin[idxr[p]] = hnr[p];
        }
    }
}

__global__ void finalize_k(float* __restrict__ out_tail) {
    int i = blockIdx.x * blockDim.x + threadIdx.x;
    if (i < Bn * HIDn) {
        out_tail[i]             = h_fin[i];
        out_tail[Bn * HIDn + i] = c_buf[i];
    }
}

extern "C" void kernel_launch(void* const* d_in, const int* in_sizes, int n_in,
                              void* d_out, int out_size) {
    const float* x    = (const float*)d_in[0];
    const float* U    = (const float*)d_in[1];
    const float* V    = (const float*)d_in[2];
    const float* bias = (const float*)d_in[3];
    const float* h0   = (const float*)d_in[4];
    const float* c0   = (const float*)d_in[5];
    float* out = (float*)d_out;

    static int attr_done = 0;
    if (!attr_done) {
        cudaFuncSetAttribute(gemm_xu_mma,
                             cudaFuncAttributeMaxDynamicSharedMemorySize, SM1);
        cudaFuncSetAttribute(lstm_persist_mma,
                             cudaFuncAttributeMaxDynamicSharedMemorySize, SM2);
        attr_done = 1;
    }

    conv_x_k<<<(int)(((size_t)Mtot * INn + 255) / 256), 256>>>(x);
    conv_uv_init_k<<<(int)((2 * (size_t)G4 * INn + 255) / 256), 256>>>(U, V, h0, c0);

    dim3 gg(G4 / 128, Mtot / 128);
    gemm_xu_mma<<<gg, 256, SM1>>>(bias);

    lstm_persist_mma<<<NCTA, NTHR, SM2>>>(out);

    long long main_elems = (long long)Bn * Sn * HIDn;
    if ((long long)out_size >= main_elems + 2LL * Bn * HIDn) {
        finalize_k<<<(Bn * HIDn + 255) / 256, 256>>>(out + main_elems);
    }
}

// round 10
// speedup vs baseline: 1.8123x; 1.3268x over previous
#include <cuda_runtime.h>
#include <cuda_bf16.h>
#include <cuda_fp16.h>
#include <stdint.h>

#define Bn   64
#define Sn   512
#define INn  1024
#define HIDn 1024
#define G4   4096
#define Mtot 32768
#define NCTA 128
#define NTHR 256

// ---- device scratch ----
__device__ float g_scr[(size_t)Mtot * G4];              // x@U + bias (512MB)
__device__ float c_buf[Bn * HIDn];
__device__ float h_fin[Bn * HIDn];
__device__ int   g_flags[Sn + 1][2];                    // per-step per-group ready counters
__device__ __half u_h[(size_t)G4 * INn];                // U^T [N][K] fp16
__device__ __half vt_h[(size_t)G4 * HIDn];              // V^T [N][K] fp16
__device__ __half hb[2][Bn * HIDn];                     // h carried as fp16

// ---- helpers ----
__device__ __forceinline__ uint32_t smem_u32(const void* p) {
    uint32_t a;
    asm("{ .reg .u64 t; cvta.to.shared.u64 t, %1; cvt.u32.u64 %0, t; }" : "=r"(a) : "l"(p));
    return a;
}
__device__ __forceinline__ void ldsm4(uint32_t r[4], uint32_t addr) {
    asm volatile("ldmatrix.sync.aligned.m8n8.x4.shared.b16 {%0,%1,%2,%3}, [%4];"
        : "=r"(r[0]), "=r"(r[1]), "=r"(r[2]), "=r"(r[3]) : "r"(addr));
}
__device__ __forceinline__ void mma_f16(float c[4], const uint32_t a[4],
                                        uint32_t b0, uint32_t b1) {
    asm volatile("mma.sync.aligned.m16n8k16.row.col.f32.f16.f16.f32 "
        "{%0,%1,%2,%3}, {%4,%5,%6,%7}, {%8,%9}, {%0,%1,%2,%3};"
        : "+f"(c[0]), "+f"(c[1]), "+f"(c[2]), "+f"(c[3])
        : "r"(a[0]), "r"(a[1]), "r"(a[2]), "r"(a[3]), "r"(b0), "r"(b1));
}
__device__ __forceinline__ float sigmoid_f(float x) { return 1.0f / (1.0f + __expf(-x)); }
__device__ __forceinline__ float tanh_f(float x) { return 2.0f / (1.0f + __expf(-2.0f * x)) - 1.0f; }

// ---------------------------------------------------------------------------
// Merged prep: U^T fp16, V^T fp16, state init, flag init.
__global__ void conv_uv_init_k(const float* __restrict__ U,
                               const float* __restrict__ V,
                               const float* __restrict__ h0,
                               const float* __restrict__ c0) {
    size_t i = (size_t)blockIdx.x * blockDim.x + threadIdx.x;
    const size_t NU = (size_t)G4 * INn;
    if (i < NU) {
        size_t n = i / INn, k = i % INn;
        u_h[i] = __float2half_rn(U[k * G4 + n]);
    } else if (i < 2 * NU) {
        size_t j = i - NU;
        size_t n = j / HIDn, k = j % HIDn;
        vt_h[j] = __float2half_rn(V[k * G4 + n]);
    }
    if (i < Bn * HIDn) {
        c_buf[i] = c0[i];
        hb[0][i] = __float2half_rn(h0[i]);
        h_fin[i] = h0[i];
    }
    if (i < (Sn + 1) * 2) ((int*)g_flags)[i] = (i < 2) ? 64 : 0;
}

// ---------------------------------------------------------------------------
// Phase 1: single-plane fp16 HMMA GEMM.  CTA 128x128, warp 32x64, kc=32,
// double-buffered. x converted fp32->fp16 in-register (no conv_x pass).
// ---------------------------------------------------------------------------
#define SA   80                  // smem row stride bytes (40 fp16)
#define TAB  (128 * SA)          // 10240 per tile
#define CHB  (2 * TAB)           // A+B per buffer
#define SM1  (2 * CHB)           // 40960

#define P1_LOADA(kc) do { \
    _Pragma("unroll") \
    for (int i = 0; i < 4; ++i) { \
        int e = tid + i * 256; int rr = e >> 3; int kq = e & 7; \
        pfA[i] = *(const float4*)(x + (size_t)(m0 + rr) * INn + (kc) * 32 + kq * 4); \
    } } while (0)
#define P1_LOADB(kc) do { \
    _Pragma("unroll") \
    for (int i = 0; i < 2; ++i) { \
        int e = tid + i * 256; int rr = e >> 2; int c = e & 3; \
        pfB[i] = *(const float4*)(u_h + (size_t)(n0 + rr) * INn + (kc) * 32 + c * 8); \
    } } while (0)
#define P1_STORE(b) do { \
    _Pragma("unroll") \
    for (int i = 0; i < 4; ++i) { \
        int e = tid + i * 256; int rr = e >> 3; int kq = e & 7; \
        __half2 h01 = __floats2half2_rn(pfA[i].x, pfA[i].y); \
        __half2 h23 = __floats2half2_rn(pfA[i].z, pfA[i].w); \
        uint2 wv; wv.x = *(uint32_t*)&h01; wv.y = *(uint32_t*)&h23; \
        *(uint2*)(sm + (b) * CHB + rr * SA + kq * 8) = wv; \
    } \
    _Pragma("unroll") \
    for (int i = 0; i < 2; ++i) { \
        int e = tid + i * 256; int rr = e >> 2; int c = e & 3; \
        *(float4*)(sm + (b) * CHB + TAB + rr * SA + c * 16) = pfB[i]; \
    } } while (0)

__global__ __launch_bounds__(256, 1) void gemm_xu_mma(const float* __restrict__ x,
                                                      const float* __restrict__ bias) {
    extern __shared__ char sm[];
    const uint32_t smb = smem_u32(sm);
    const int tid = threadIdx.x, w = tid >> 5, l = tid & 31;
    const int m0 = blockIdx.y * 128, n0 = blockIdx.x * 128;
    const int wm = w >> 1, wn = w & 1;
    const int gr = l >> 2, q = l & 3;
    const int rA = (l & 7) + ((l >> 3) & 1) * 8, cA = (l >> 4) * 16;
    const int rB = (l & 7) + ((l >> 4) & 1) * 8, cB = ((l >> 3) & 1) * 16;

    float acc[2][8][4];
#pragma unroll
    for (int a = 0; a < 2; ++a)
#pragma unroll
        for (int b = 0; b < 8; ++b)
#pragma unroll
            for (int c = 0; c < 4; ++c) acc[a][b][c] = 0.0f;

    float4 pfA[4], pfB[2];
    P1_LOADA(0);
    P1_LOADB(0);
    P1_STORE(0);
    P1_LOADA(1);
    P1_LOADB(1);
    __syncthreads();

    for (int kc = 0; kc < 32; ++kc) {
        const int buf = kc & 1;
        if (kc + 1 < 32) P1_STORE(buf ^ 1);
        if (kc + 2 < 32) { P1_LOADA(kc + 2); P1_LOADB(kc + 2); }

        const uint32_t base = smb + buf * CHB;
#pragma unroll
        for (int ks = 0; ks < 2; ++ks) {
            uint32_t ah[2][4];
#pragma unroll
            for (int mfi = 0; mfi < 2; ++mfi) {
                uint32_t ra = base + (uint32_t)((wm * 32 + mfi * 16 + rA) * SA + ks * 32 + cA);
                ldsm4(ah[mfi], ra);
            }
#pragma unroll
            for (int np = 0; np < 4; ++np) {
                uint32_t rb = base + TAB +
                              (uint32_t)((wn * 64 + np * 16 + rB) * SA + ks * 32 + cB);
                uint32_t bh[4];
                ldsm4(bh, rb);
#pragma unroll
                for (int mfi = 0; mfi < 2; ++mfi) {
                    mma_f16(acc[mfi][2 * np],     ah[mfi], bh[0], bh[1]);
                    mma_f16(acc[mfi][2 * np + 1], ah[mfi], bh[2], bh[3]);
                }
            }
        }
        __syncthreads();
    }

#pragma unroll
    for (int mfi = 0; mfi < 2; ++mfi) {
#pragma unroll
        for (int nf = 0; nf < 8; ++nf) {
            int row = m0 + wm * 32 + mfi * 16 + gr;
            int col = n0 + wn * 64 + nf * 8 + 2 * q;
            float2 bz = *(const float2*)(bias + col);
            float2 w0 = make_float2(acc[mfi][nf][0] + bz.x, acc[mfi][nf][1] + bz.y);
            float2 w1 = make_float2(acc[mfi][nf][2] + bz.x, acc[mfi][nf][3] + bz.y);
            *(float2*)(g_scr + (size_t)row * G4 + col) = w0;
            *(float2*)(g_scr + (size_t)(row + 8) * G4 + col) = w1;
        }
    }
}

// ---------------------------------------------------------------------------
// Phase 2: BATCH-SPLIT persistent recurrence (unchanged from R9 — known good).
// ---------------------------------------------------------------------------
#define KP2    2064
#define HB_OFF (64 * KP2)
#define HROW   1040
#define HBUF   (32 * HROW)
#define GSM_O  (HB_OFF + 2 * HBUF)
#define SM2    (GSM_O + 32 * 68 * 4)

#define POLL_FLAG(pt) do { \
    if (l == 0) { \
        const int* _fp = &g_flags[(pt)][gid]; \
        int _v, _sp = 0; \
        for (;;) { \
            asm volatile("ld.acquire.gpu.global.s32 %0, [%1];" : "=r"(_v) : "l"(_fp) : "memory"); \
            if (_v >= 64) break; \
            if (++_sp > 16) { __nanosleep(64); _sp = 0; } \
        } \
    } \
    __syncwarp(); } while (0)

#define P2_ISSUE(ch) do { \
    _Pragma("unroll") \
    for (int i = 0; i < 8; ++i) { \
        int e = tid + i * 256; int rr = e >> 6; int c16 = e & 63; \
        uint32_t dst = smb + HB_OFF + (ch) * HBUF + rr * HROW + c16 * 16; \
        const __half* src = hh + (size_t)rr * HIDn + (ch) * 512 + c16 * 8; \
        asm volatile("cp.async.cg.shared.global [%0], [%1], 16;" :: "r"(dst), "l"(src) : "memory"); \
    } \
    asm volatile("cp.async.commit_group;" ::: "memory"); } while (0)

#define P2_COMPUTE(ch) do { \
    const uint32_t ab = smb + HB_OFF + (ch) * HBUF + (uint32_t)((mf * 16 + rA) * HROW + cA); \
    const uint32_t bb = smb + (uint32_t)((nb + rB) * KP2 + (ch) * 1024 + cB); \
    _Pragma("unroll") \
    for (int ks = 0; ks < 32; ++ks) { \
        uint32_t a4[4], b4[4]; \
        ldsm4(a4, ab + ks * 32); \
        ldsm4(b4, bb + ks * 32); \
        mma_f16(acc[0], a4, b4[0], b4[1]); \
        mma_f16(acc[1], a4, b4[2], b4[3]); \
    } } while (0)

__global__ __launch_bounds__(NTHR, 1) void lstm_persist_mma(float* __restrict__ out) {
    extern __shared__ char sm[];
    const uint32_t smb = smem_u32(sm);
    float* gsm = (float*)(sm + GSM_O);
    const int tid = threadIdx.x, w = tid >> 5, l = tid & 31;
    const int gid   = blockIdx.x & 1;
    const int cid   = blockIdx.x >> 1;
    const int j0    = cid * 16;
    const int rbase = gid * 32;
    const int mf = w >> 2, nb = (w & 3) * 16;
    const int gr = l >> 2, q = l & 3;
    const int rA = (l & 7) + ((l >> 3) & 1) * 8, cA = (l >> 4) * 16;
    const int rB = (l & 7) + ((l >> 4) & 1) * 8, cB = ((l >> 3) & 1) * 16;

    // Load V^T slice (64 gate-cols x 1024 k, fp16) once: 128KB.
#pragma unroll
    for (int i = 0; i < 32; ++i) {
        int e = tid + i * 256;
        int r = e >> 7, c = e & 127;
        int gv = (r >> 4) * 1024 + j0 + (r & 15);
        *(float4*)(sm + r * KP2 + c * 16) = *(const float4*)(vt_h + (size_t)gv * HIDn + c * 8);
    }
    __syncthreads();

    for (int t = 0; t < Sn; ++t) {
        const __half* hh  = hb[t & 1] + (size_t)rbase * HIDn;
        const int     nxt = (t & 1) ^ 1;

        // Prefetch x@U+bias (independent of flags; overlaps poll).
        float2 gpre[4];
        {
            int m = rbase + mf * 16 + gr;
            const float* gp = g_scr + ((size_t)(m * Sn + t)) * G4;
#pragma unroll
            for (int nf = 0; nf < 2; ++nf) {
                int c = nb + nf * 8 + 2 * q;
                int gcol = (c >> 4) * HIDn + j0 + (c & 15);
                gpre[nf * 2]     = *(const float2*)(gp + gcol);
                gpre[nf * 2 + 1] = *(const float2*)(gp + (size_t)8 * Sn * G4 + gcol);
            }
        }

        float acc[2][4];
#pragma unroll
        for (int a = 0; a < 2; ++a)
#pragma unroll
            for (int c = 0; c < 4; ++c) acc[a][c] = 0.0f;

        POLL_FLAG(t);
        P2_ISSUE(0);
        P2_ISSUE(1);

        asm volatile("cp.async.wait_group 1;" ::: "memory");
        __syncthreads();
        P2_COMPUTE(0);
        asm volatile("cp.async.wait_group 0;" ::: "memory");
        __syncthreads();
        P2_COMPUTE(1);

        // Stage pre-activations into gsm [32 rows][64 gate-cols, stride 68].
#pragma unroll
        for (int nf = 0; nf < 2; ++nf) {
            int m = mf * 16 + gr;
            int c = nb + nf * 8 + 2 * q;
            gsm[m * 68 + c]           = acc[nf][0] + gpre[nf * 2].x;
            gsm[m * 68 + c + 1]       = acc[nf][1] + gpre[nf * 2].y;
            gsm[(m + 8) * 68 + c]     = acc[nf][2] + gpre[nf * 2 + 1].x;
            gsm[(m + 8) * 68 + c + 1] = acc[nf][3] + gpre[nf * 2 + 1].y;
        }
        __syncthreads();

        // Gates: 32 rows x 16 h-cols = 512 cells, 2 per thread.
        float cnr[2], hnr[2];
        int   idxr[2];
#pragma unroll
        for (int p = 0; p < 2; ++p) {
            int e  = tid + p * 256;
            int m  = e >> 4;
            int jj = e & 15;
            float gn = gsm[m * 68 + jj];
            float gi = gsm[m * 68 + 16 + jj];
            float gf = gsm[m * 68 + 32 + jj];
            float go = gsm[m * 68 + 48 + jj];
            float nv = tanh_f(gn);
            float iv = sigmoid_f(gi);
            float fv = sigmoid_f(gf);
            float ov = sigmoid_f(go);
            int idx = (rbase + m) * HIDn + j0 + jj;
            float cn = c_buf[idx] * fv + nv * iv;
            float hn = tanh_f(cn) * ov;
            hb[nxt][idx] = __float2half_rn(hn);
            cnr[p] = cn; hnr[p] = hn; idxr[p] = idx;
        }

        // Publish: this CTA's h cols for step t+1 are ready (group flag).
        __syncthreads();
        if (tid == 0) {
            const int* fp = &g_flags[t + 1][gid];
            asm volatile("red.release.gpu.global.add.s32 [%0], %1;"
                         :: "l"(fp), "r"(1) : "memory");
        }

        // Deferred stores (off the inter-CTA critical path).
#pragma unroll
        for (int p = 0; p < 2; ++p) {
            int e  = tid + p * 256;
            int m  = e >> 4;
            int jj = e & 15;
            c_buf[idxr[p]] = cnr[p];
            out[((size_t)(rbase + m) * Sn + t) * HIDn + j0 + jj] = hnr[p];
            if (t == Sn - 1) h_fin[idxr[p]] = hnr[p];
        }
    }
}

__global__ void finalize_k(float* __restrict__ out_tail) {
    int i = blockIdx.x * blockDim.x + threadIdx.x;
    if (i < Bn * HIDn) {
        out_tail[i]             = h_fin[i];
        out_tail[Bn * HIDn + i] = c_buf[i];
    }
}

extern "C" void kernel_launch(void* const* d_in, const int* in_sizes, int n_in,
                              void* d_out, int out_size) {
    const float* x    = (const float*)d_in[0];
    const float* U    = (const float*)d_in[1];
    const float* V    = (const float*)d_in[2];
    const float* bias = (const float*)d_in[3];
    const float* h0   = (const float*)d_in[4];
    const float* c0   = (const float*)d_in[5];
    float* out = (float*)d_out;

    static int attr_done = 0;
    if (!attr_done) {
        cudaFuncSetAttribute(gemm_xu_mma,
                             cudaFuncAttributeMaxDynamicSharedMemorySize, SM1);
        cudaFuncSetAttribute(lstm_persist_mma,
                             cudaFuncAttributeMaxDynamicSharedMemorySize, SM2);
        attr_done = 1;
    }

    conv_uv_init_k<<<(int)((2 * (size_t)G4 * INn + 255) / 256), 256>>>(U, V, h0, c0);

    dim3 gg(G4 / 128, Mtot / 128);
    gemm_xu_mma<<<gg, 256, SM1>>>(x, bias);

    lstm_persist_mma<<<NCTA, NTHR, SM2>>>(out);

    long long main_elems = (long long)Bn * Sn * HIDn;
    if ((long long)out_size >= main_elems + 2LL * Bn * HIDn) {
        finalize_k<<<(Bn * HIDn + 255) / 256, 256>>>(out + main_elems);
    }
}

// round 11
// speedup vs baseline: 1.9618x; 1.0825x over previous
#include <cuda_runtime.h>
#include <cuda_bf16.h>
#include <cuda_fp16.h>
#include <stdint.h>

#define Bn   64
#define Sn   512
#define INn  1024
#define HIDn 1024
#define G4   4096
#define Mtot 32768
#define NCTA 128
#define NTHR 256

// ---- device scratch ----
__device__ float g_scr[(size_t)Mtot * G4];              // x@U + bias (512MB)
__device__ float c_buf[Bn * HIDn];
__device__ float h_fin[Bn * HIDn];
__device__ int   g_flags[Sn + 1][2];                    // per-step per-group ready counters
__device__ __half u_h[(size_t)G4 * INn];                // U^T [N][K] fp16
__device__ __half vt_h[(size_t)G4 * HIDn];              // V^T [N][K] fp16
__device__ __half hb[2][Bn * HIDn];                     // h carried as fp16

// ---- helpers ----
__device__ __forceinline__ uint32_t smem_u32(const void* p) {
    uint32_t a;
    asm("{ .reg .u64 t; cvta.to.shared.u64 t, %1; cvt.u32.u64 %0, t; }" : "=r"(a) : "l"(p));
    return a;
}
__device__ __forceinline__ void ldsm4(uint32_t r[4], uint32_t addr) {
    asm volatile("ldmatrix.sync.aligned.m8n8.x4.shared.b16 {%0,%1,%2,%3}, [%4];"
        : "=r"(r[0]), "=r"(r[1]), "=r"(r[2]), "=r"(r[3]) : "r"(addr));
}
__device__ __forceinline__ void mma_f16(float c[4], const uint32_t a[4],
                                        uint32_t b0, uint32_t b1) {
    asm volatile("mma.sync.aligned.m16n8k16.row.col.f32.f16.f16.f32 "
        "{%0,%1,%2,%3}, {%4,%5,%6,%7}, {%8,%9}, {%0,%1,%2,%3};"
        : "+f"(c[0]), "+f"(c[1]), "+f"(c[2]), "+f"(c[3])
        : "r"(a[0]), "r"(a[1]), "r"(a[2]), "r"(a[3]), "r"(b0), "r"(b1));
}
// HW tanh unit (MUFU.TANH, sm_75+): 1 MUFU op vs EX2+RCP(+Newton) chains.
__device__ __forceinline__ float tanh_f(float x) {
    float y;
    asm("tanh.approx.f32 %0, %1;" : "=f"(y) : "f"(x));
    return y;
}
__device__ __forceinline__ float sigmoid_f(float x) {
    return fmaf(0.5f, tanh_f(0.5f * x), 0.5f);
}

// ---------------------------------------------------------------------------
// Merged prep: U^T fp16, V^T fp16, state init, flag init.
__global__ void conv_uv_init_k(const float* __restrict__ U,
                               const float* __restrict__ V,
                               const float* __restrict__ h0,
                               const float* __restrict__ c0) {
    size_t i = (size_t)blockIdx.x * blockDim.x + threadIdx.x;
    const size_t NU = (size_t)G4 * INn;
    if (i < NU) {
        size_t n = i / INn, k = i % INn;
        u_h[i] = __float2half_rn(U[k * G4 + n]);
    } else if (i < 2 * NU) {
        size_t j = i - NU;
        size_t n = j / HIDn, k = j % HIDn;
        vt_h[j] = __float2half_rn(V[k * G4 + n]);
    }
    if (i < Bn * HIDn) {
        c_buf[i] = c0[i];
        hb[0][i] = __float2half_rn(h0[i]);
        h_fin[i] = h0[i];
    }
    if (i < (Sn + 1) * 2) ((int*)g_flags)[i] = (i < 2) ? 64 : 0;
}

// ---------------------------------------------------------------------------
// Phase 1: single-plane fp16 HMMA GEMM (unchanged from R10 — known good).
// ---------------------------------------------------------------------------
#define SA   80
#define TAB  (128 * SA)
#define CHB  (2 * TAB)
#define SM1  (2 * CHB)

#define P1_LOADA(kc) do { \
    _Pragma("unroll") \
    for (int i = 0; i < 4; ++i) { \
        int e = tid + i * 256; int rr = e >> 3; int kq = e & 7; \
        pfA[i] = *(const float4*)(x + (size_t)(m0 + rr) * INn + (kc) * 32 + kq * 4); \
    } } while (0)
#define P1_LOADB(kc) do { \
    _Pragma("unroll") \
    for (int i = 0; i < 2; ++i) { \
        int e = tid + i * 256; int rr = e >> 2; int c = e & 3; \
        pfB[i] = *(const float4*)(u_h + (size_t)(n0 + rr) * INn + (kc) * 32 + c * 8); \
    } } while (0)
#define P1_STORE(b) do { \
    _Pragma("unroll") \
    for (int i = 0; i < 4; ++i) { \
        int e = tid + i * 256; int rr = e >> 3; int kq = e & 7; \
        __half2 h01 = __floats2half2_rn(pfA[i].x, pfA[i].y); \
        __half2 h23 = __floats2half2_rn(pfA[i].z, pfA[i].w); \
        uint2 wv; wv.x = *(uint32_t*)&h01; wv.y = *(uint32_t*)&h23; \
        *(uint2*)(sm + (b) * CHB + rr * SA + kq * 8) = wv; \
    } \
    _Pragma("unroll") \
    for (int i = 0; i < 2; ++i) { \
        int e = tid + i * 256; int rr = e >> 2; int c = e & 3; \
        *(float4*)(sm + (b) * CHB + TAB + rr * SA + c * 16) = pfB[i]; \
    } } while (0)

__global__ __launch_bounds__(256, 1) void gemm_xu_mma(const float* __restrict__ x,
                                                      const float* __restrict__ bias) {
    extern __shared__ char sm[];
    const uint32_t smb = smem_u32(sm);
    const int tid = threadIdx.x, w = tid >> 5, l = tid & 31;
    const int m0 = blockIdx.y * 128, n0 = blockIdx.x * 128;
    const int wm = w >> 1, wn = w & 1;
    const int gr = l >> 2, q = l & 3;
    const int rA = (l & 7) + ((l >> 3) & 1) * 8, cA = (l >> 4) * 16;
    const int rB = (l & 7) + ((l >> 4) & 1) * 8, cB = ((l >> 3) & 1) * 16;

    float acc[2][8][4];
#pragma unroll
    for (int a = 0; a < 2; ++a)
#pragma unroll
        for (int b = 0; b < 8; ++b)
#pragma unroll
            for (int c = 0; c < 4; ++c) acc[a][b][c] = 0.0f;

    float4 pfA[4], pfB[2];
    P1_LOADA(0);
    P1_LOADB(0);
    P1_STORE(0);
    P1_LOADA(1);
    P1_LOADB(1);
    __syncthreads();

    for (int kc = 0; kc < 32; ++kc) {
        const int buf = kc & 1;
        if (kc + 1 < 32) P1_STORE(buf ^ 1);
        if (kc + 2 < 32) { P1_LOADA(kc + 2); P1_LOADB(kc + 2); }

        const uint32_t base = smb + buf * CHB;
#pragma unroll
        for (int ks = 0; ks < 2; ++ks) {
            uint32_t ah[2][4];
#pragma unroll
            for (int mfi = 0; mfi < 2; ++mfi) {
                uint32_t ra = base + (uint32_t)((wm * 32 + mfi * 16 + rA) * SA + ks * 32 + cA);
                ldsm4(ah[mfi], ra);
            }
#pragma unroll
            for (int np = 0; np < 4; ++np) {
                uint32_t rb = base + TAB +
                              (uint32_t)((wn * 64 + np * 16 + rB) * SA + ks * 32 + cB);
                uint32_t bh[4];
                ldsm4(bh, rb);
#pragma unroll
                for (int mfi = 0; mfi < 2; ++mfi) {
                    mma_f16(acc[mfi][2 * np],     ah[mfi], bh[0], bh[1]);
                    mma_f16(acc[mfi][2 * np + 1], ah[mfi], bh[2], bh[3]);
                }
            }
        }
        __syncthreads();
    }

#pragma unroll
    for (int mfi = 0; mfi < 2; ++mfi) {
#pragma unroll
        for (int nf = 0; nf < 8; ++nf) {
            int row = m0 + wm * 32 + mfi * 16 + gr;
            int col = n0 + wn * 64 + nf * 8 + 2 * q;
            float2 bz = *(const float2*)(bias + col);
            float2 w0 = make_float2(acc[mfi][nf][0] + bz.x, acc[mfi][nf][1] + bz.y);
            float2 w1 = make_float2(acc[mfi][nf][2] + bz.x, acc[mfi][nf][3] + bz.y);
            *(float2*)(g_scr + (size_t)row * G4 + col) = w0;
            *(float2*)(g_scr + (size_t)(row + 8) * G4 + col) = w1;
        }
    }
}

// ---------------------------------------------------------------------------
// Phase 2: BATCH-SPLIT persistent recurrence (R9 structure), gate epilogue
// rewritten onto the HW tanh unit (MUFU.TANH) — the step-critical-path cost.
// ---------------------------------------------------------------------------
#define KP2    2064
#define HB_OFF (64 * KP2)
#define HROW   1040
#define HBUF   (32 * HROW)
#define GSM_O  (HB_OFF + 2 * HBUF)
#define SM2    (GSM_O + 32 * 68 * 4)

#define POLL_FLAG(pt) do { \
    if (l == 0) { \
        const int* _fp = &g_flags[(pt)][gid]; \
        int _v, _sp = 0; \
        for (;;) { \
            asm volatile("ld.acquire.gpu.global.s32 %0, [%1];" : "=r"(_v) : "l"(_fp) : "memory"); \
            if (_v >= 64) break; \
            if (++_sp > 16) { __nanosleep(64); _sp = 0; } \
        } \
    } \
    __syncwarp(); } while (0)

#define P2_ISSUE(ch) do { \
    _Pragma("unroll") \
    for (int i = 0; i < 8; ++i) { \
        int e = tid + i * 256; int rr = e >> 6; int c16 = e & 63; \
        uint32_t dst = smb + HB_OFF + (ch) * HBUF + rr * HROW + c16 * 16; \
        const __half* src = hh + (size_t)rr * HIDn + (ch) * 512 + c16 * 8; \
        asm volatile("cp.async.cg.shared.global [%0], [%1], 16;" :: "r"(dst), "l"(src) : "memory"); \
    } \
    asm volatile("cp.async.commit_group;" ::: "memory"); } while (0)

#define P2_COMPUTE(ch) do { \
    const uint32_t ab = smb + HB_OFF + (ch) * HBUF + (uint32_t)((mf * 16 + rA) * HROW + cA); \
    const uint32_t bb = smb + (uint32_t)((nb + rB) * KP2 + (ch) * 1024 + cB); \
    _Pragma("unroll") \
    for (int ks = 0; ks < 32; ++ks) { \
        uint32_t a4[4], b4[4]; \
        ldsm4(a4, ab + ks * 32); \
        ldsm4(b4, bb + ks * 32); \
        mma_f16(acc[0], a4, b4[0], b4[1]); \
        mma_f16(acc[1], a4, b4[2], b4[3]); \
    } } while (0)

__global__ __launch_bounds__(NTHR, 1) void lstm_persist_mma(float* __restrict__ out) {
    extern __shared__ char sm[];
    const uint32_t smb = smem_u32(sm);
    float* gsm = (float*)(sm + GSM_O);
    const int tid = threadIdx.x, w = tid >> 5, l = tid & 31;
    const int gid   = blockIdx.x & 1;
    const int cid   = blockIdx.x >> 1;
    const int j0    = cid * 16;
    const int rbase = gid * 32;
    const int mf = w >> 2, nb = (w & 3) * 16;
    const int gr = l >> 2, q = l & 3;
    const int rA = (l & 7) + ((l >> 3) & 1) * 8, cA = (l >> 4) * 16;
    const int rB = (l & 7) + ((l >> 4) & 1) * 8, cB = ((l >> 3) & 1) * 16;

    // Load V^T slice (64 gate-cols x 1024 k, fp16) once: 128KB.
#pragma unroll
    for (int i = 0; i < 32; ++i) {
        int e = tid + i * 256;
        int r = e >> 7, c = e & 127;
        int gv = (r >> 4) * 1024 + j0 + (r & 15);
        *(float4*)(sm + r * KP2 + c * 16) = *(const float4*)(vt_h + (size_t)gv * HIDn + c * 8);
    }
    __syncthreads();

    for (int t = 0; t < Sn; ++t) {
        const __half* hh  = hb[t & 1] + (size_t)rbase * HIDn;
        const int     nxt = (t & 1) ^ 1;

        // Prefetch x@U+bias (independent of flags; overlaps poll).
        float2 gpre[4];
        {
            int m = rbase + mf * 16 + gr;
            const float* gp = g_scr + ((size_t)(m * Sn + t)) * G4;
#pragma unroll
            for (int nf = 0; nf < 2; ++nf) {
                int c = nb + nf * 8 + 2 * q;
                int gcol = (c >> 4) * HIDn + j0 + (c & 15);
                gpre[nf * 2]     = *(const float2*)(gp + gcol);
                gpre[nf * 2 + 1] = *(const float2*)(gp + (size_t)8 * Sn * G4 + gcol);
            }
        }

        float acc[2][4];
#pragma unroll
        for (int a = 0; a < 2; ++a)
#pragma unroll
            for (int c = 0; c < 4; ++c) acc[a][c] = 0.0f;

        POLL_FLAG(t);
        P2_ISSUE(0);
        P2_ISSUE(1);

        asm volatile("cp.async.wait_group 1;" ::: "memory");
        __syncthreads();
        P2_COMPUTE(0);
        asm volatile("cp.async.wait_group 0;" ::: "memory");
        __syncthreads();
        P2_COMPUTE(1);

        // Stage pre-activations into gsm [32 rows][64 gate-cols, stride 68].
#pragma unroll
        for (int nf = 0; nf < 2; ++nf) {
            int m = mf * 16 + gr;
            int c = nb + nf * 8 + 2 * q;
            gsm[m * 68 + c]           = acc[nf][0] + gpre[nf * 2].x;
            gsm[m * 68 + c + 1]       = acc[nf][1] + gpre[nf * 2].y;
            gsm[(m + 8) * 68 + c]     = acc[nf][2] + gpre[nf * 2 + 1].x;
            gsm[(m + 8) * 68 + c + 1] = acc[nf][3] + gpre[nf * 2 + 1].y;
        }
        __syncthreads();

        // Gates: 32 rows x 16 h-cols = 512 cells, 2 per thread. MUFU.TANH path.
        float cnr[2], hnr[2];
        int   idxr[2];
#pragma unroll
        for (int p = 0; p < 2; ++p) {
            int e  = tid + p * 256;
            int m  = e >> 4;
            int jj = e & 15;
            float gn = gsm[m * 68 + jj];
            float gi = gsm[m * 68 + 16 + jj];
            float gf = gsm[m * 68 + 32 + jj];
            float go = gsm[m * 68 + 48 + jj];
            float nv = tanh_f(gn);
            float iv = sigmoid_f(gi);
            float fv = sigmoid_f(gf);
            float ov = sigmoid_f(go);
            int idx = (rbase + m) * HIDn + j0 + jj;
            float cn = c_buf[idx] * fv + nv * iv;
            float hn = tanh_f(cn) * ov;
            hb[nxt][idx] = __float2half_rn(hn);
            cnr[p] = cn; hnr[p] = hn; idxr[p] = idx;
        }

        // Publish: this CTA's h cols for step t+1 are ready (group flag).
        __syncthreads();
        if (tid == 0) {
            const int* fp = &g_flags[t + 1][gid];
            asm volatile("red.release.gpu.global.add.s32 [%0], %1;"
                         :: "l"(fp), "r"(1) : "memory");
        }

        // Deferred stores (off the inter-CTA critical path).
#pragma unroll
        for (int p = 0; p < 2; ++p) {
            int e  = tid + p * 256;
            int m  = e >> 4;
            int jj = e & 15;
            c_buf[idxr[p]] = cnr[p];
            out[((size_t)(rbase + m) * Sn + t) * HIDn + j0 + jj] = hnr[p];
            if (t == Sn - 1) h_fin[idxr[p]] = hnr[p];
        }
    }
}

__global__ void finalize_k(float* __restrict__ out_tail) {
    int i = blockIdx.x * blockDim.x + threadIdx.x;
    if (i < Bn * HIDn) {
        out_tail[i]             = h_fin[i];
        out_tail[Bn * HIDn + i] = c_buf[i];
    }
}

extern "C" void kernel_launch(void* const* d_in, const int* in_sizes, int n_in,
                              void* d_out, int out_size) {
    const float* x    = (const float*)d_in[0];
    const float* U    = (const float*)d_in[1];
    const float* V    = (const float*)d_in[2];
    const float* bias = (const float*)d_in[3];
    const float* h0   = (const float*)d_in[4];
    const float* c0   = (const float*)d_in[5];
    float* out = (float*)d_out;

    static int attr_done = 0;
    if (!attr_done) {
        cudaFuncSetAttribute(gemm_xu_mma,
                             cudaFuncAttributeMaxDynamicSharedMemorySize, SM1);
        cudaFuncSetAttribute(lstm_persist_mma,
                             cudaFuncAttributeMaxDynamicSharedMemorySize, SM2);
        attr_done = 1;
    }

    conv_uv_init_k<<<(int)((2 * (size_t)G4 * INn + 255) / 256), 256>>>(U, V, h0, c0);

    dim3 gg(G4 / 128, Mtot / 128);
    gemm_xu_mma<<<gg, 256, SM1>>>(x, bias);

    lstm_persist_mma<<<NCTA, NTHR, SM2>>>(out);

    long long main_elems = (long long)Bn * Sn * HIDn;
    if ((long long)out_size >= main_elems + 2LL * Bn * HIDn) {
        finalize_k<<<(Bn * HIDn + 255) / 256, 256>>>(out + main_elems);
    }
}